// round 6
// baseline (speedup 1.0000x reference)
#include <cuda_runtime.h>
#include <cstdint>

// FixedGaussianBlur: depthwise 21x21 Gaussian (sigma=3), reflect padding,
// x[32,3,512,512] f32 -> y[32,3,512,512] f32.
// Separable, fused, in-place smem tile. TW=64, TH=128, halo left 12 / right 10
// -> 148x88 data in a 148x90-stride tile (53.3 KB, 3 blocks/SM).
// Horizontal: STREAMING packed f32x2 over column pairs (even pairs free from
// LDS.64, odd pairs built transiently -> ~22 live regs). Vertical: packed
// f32x2 over col pairs, 8-row groups, conflict-free.

#define IMG_W 512
#define IMG_H 512
#define PAD 10
#define HALO_L 12          // left halo widened to 12 for 16B-aligned loads
#define KS 21
#define TW 64
#define TH 128
#define SROWS 148          // TH + 20
#define SCOLS 90           // 88 data cols + 2 pad (stride 90: 2-way banks max)
#define DATA_COLS 88       // gmem cols x0-12 .. x0+75
#define NTHREADS 512
#define NIMG 96
#define SMEM_BYTES (SROWS * SCOLS * 4)   // 53280

#define W0  0.13303900f
#define W1  0.12584950f
#define W2  0.10652928f
#define W3  0.08069223f
#define W4  0.05469397f
#define W5  0.03317359f
#define W6  0.01800488f
#define W7  0.00874446f
#define W8  0.00380033f
#define W9  0.00147793f
#define W10 0.00051432f

__device__ __forceinline__ float tap(int j) {
    constexpr float w[KS] = {W10, W9, W8, W7, W6, W5, W4, W3, W2, W1, W0,
                             W1, W2, W3, W4, W5, W6, W7, W8, W9, W10};
    return w[j];
}

__device__ __forceinline__ int reflect_idx(int i, int n) {
    i = (i < 0) ? -i : i;
    i = (i >= n) ? (2 * n - 2 - i) : i;
    return i;
}

__device__ __forceinline__ uint64_t bcast2(float f) {
    uint32_t b = __float_as_uint(f);
    return ((uint64_t)b << 32) | (uint64_t)b;
}

__device__ __forceinline__ uint64_t pkf2(float lo, float hi) {
    uint64_t r;
    asm("mov.b64 %0, {%1, %2};" : "=l"(r) : "f"(lo), "f"(hi));
    return r;
}

__device__ __forceinline__ void ffma2(uint64_t& d, uint64_t a, uint64_t b, uint64_t c) {
    asm("fma.rn.f32x2 %0, %1, %2, %3;" : "=l"(d) : "l"(a), "l"(b), "l"(c));
}

// Streaming packed horizontal filter: NP output pairs (2*NP outputs).
// win points at smem col (oc0 + 2) of the row. acc[p] covers outputs 2p,2p+1.
// out[c] = sum_j w[j] * win[c + j], window read as even pairs E[k]=(win[2k],win[2k+1]).
template <int NP>
__device__ __forceinline__ void hfilter_stream(const float* __restrict__ win,
                                               uint64_t acc[NP]) {
    #pragma unroll
    for (int p = 0; p < NP; ++p) acc[p] = 0;
    float2 eprev;
    #pragma unroll
    for (int k = 0; k < NP + 10; ++k) {
        float2 e = *reinterpret_cast<const float2*>(win + 2 * k);
        uint64_t Ek = pkf2(e.x, e.y);
        #pragma unroll
        for (int p = 0; p < NP; ++p) {
            int m = k - p;                       // even tap j = 2m
            if (m >= 0 && m <= 10) ffma2(acc[p], Ek, bcast2(tap(2 * m)), acc[p]);
        }
        if (k > 0) {
            uint64_t Ok = pkf2(eprev.y, e.x);    // odd pair (win[2k-1], win[2k])
            #pragma unroll
            for (int p = 0; p < NP; ++p) {
                int m = (k - 1) - p;             // odd tap j = 2m+1
                if (m >= 0 && m <= 9) ffma2(acc[p], Ok, bcast2(tap(2 * m + 1)), acc[p]);
            }
        }
        eprev = e;
    }
}

__global__ __launch_bounds__(NTHREADS, 3)
void gauss_blur_fused(const float* __restrict__ in, float* __restrict__ out) {
    extern __shared__ __align__(16) float s[];   // [SROWS][SCOLS], col c <-> gmem x0-12+c

    const int tid = threadIdx.x;
    const int x0 = blockIdx.x * TW;
    const int y0 = blockIdx.y * TH;
    const float* __restrict__ base = in + (size_t)blockIdx.z * (IMG_W * IMG_H);

    // ---- Load 148x88 tile (y reflected; x reflected only on edge blocks) ----
    const bool x_int = (x0 >= HALO_L) && (x0 - HALO_L + DATA_COLS <= IMG_W);
    if (x_int) {
        // 148 rows x 22 float4 = 3256 aligned LDG.128
        int idx = tid;
        #pragma unroll
        for (int it = 0; it < 7; ++it) {
            if (idx < SROWS * 22) {
                int r = idx / 22;
                int k = idx - r * 22;
                int gy = reflect_idx(y0 - PAD + r, IMG_H);
                float4 v = __ldg((const float4*)(base + (size_t)gy * IMG_W
                                                 + (x0 - HALO_L) + 4 * k));
                float* d = s + r * SCOLS + 4 * k;
                *reinterpret_cast<float2*>(d)     = make_float2(v.x, v.y);
                *reinterpret_cast<float2*>(d + 2) = make_float2(v.z, v.w);
            }
            idx += NTHREADS;
        }
    } else {
        int idx = tid;
        #pragma unroll
        for (int it = 0; it < 26; ++it) {
            if (idx < SROWS * DATA_COLS) {
                int r = idx / DATA_COLS;
                int c = idx - r * DATA_COLS;
                int gy = reflect_idx(y0 - PAD + r, IMG_H);
                int gx = reflect_idx(x0 - HALO_L + c, IMG_W);
                s[r * SCOLS + c] = __ldg(base + (size_t)gy * IMG_W + gx);
            }
            idx += NTHREADS;
        }
    }
    __syncthreads();

    // ---- Horizontal pass, in place, rows-disjoint phases ----
    // P1: rows 0..127, 512 units of 16 outputs (1 per thread).
    // P2: rows 128..147, 160 units of 8 outputs (threads 0..159).
    {
        const int row1 = tid >> 2;                 // 0..127
        const int oc0a = (tid & 3) << 4;           // 0,16,32,48
        uint64_t acc1[8];
        hfilter_stream<8>(&s[row1 * SCOLS + oc0a + 2], acc1);
        __syncthreads();                           // all P1 reads complete

        {   // P1 store: h-values at cols oc0+12 .. oc0+27
            uint64_t* dst = reinterpret_cast<uint64_t*>(&s[row1 * SCOLS + oc0a + 12]);
            #pragma unroll
            for (int p = 0; p < 8; ++p) dst[p] = acc1[p];
        }

        // P2 compute: rows 128..147 (raw rows untouched by P1 stores)
        const bool p2 = (tid < 160);
        const int row2 = 128 + (tid >> 3);
        const int oc0b = (tid & 7) << 3;           // 0,8,...,56
        uint64_t acc2[4];
        if (p2) hfilter_stream<4>(&s[row2 * SCOLS + oc0b + 2], acc2);
        __syncthreads();                           // P2 reads done + P1 stores visible
        if (p2) {
            uint64_t* dst = reinterpret_cast<uint64_t*>(&s[row2 * SCOLS + oc0b + 12]);
            #pragma unroll
            for (int p = 0; p < 4; ++p) dst[p] = acc2[p];
        }
    }
    __syncthreads();

    // ---- Vertical pass: 32 col-pairs x 16 groups of 8 rows ----
    {
        const int cp = tid & 31;                   // cols 2cp, 2cp+1 (smem col 12+2cp)
        const int g = (tid >> 5) << 3;             // first output row: 0,8,...,120

        uint64_t acc[8];
        #pragma unroll
        for (int o = 0; o < 8; ++o) acc[o] = 0;

        const float* col = s + 12 + 2 * cp;
        #pragma unroll
        for (int t = 0; t < 28; ++t) {
            uint64_t v2 = *reinterpret_cast<const uint64_t*>(col + (g + t) * SCOLS);
            #pragma unroll
            for (int o = 0; o < 8; ++o) {
                int j = t - o;
                if (j >= 0 && j < KS) ffma2(acc[o], v2, bcast2(tap(j)), acc[o]);
            }
        }

        char* dst = (char*)(out + (size_t)blockIdx.z * (IMG_W * IMG_H)
                                + (size_t)(y0 + g) * IMG_W + (x0 + 2 * cp));
        #pragma unroll
        for (int o = 0; o < 8; ++o)
            *reinterpret_cast<uint64_t*>(dst + (size_t)o * IMG_W * 4) = acc[o];
    }
}

extern "C" void kernel_launch(void* const* d_in, const int* in_sizes, int n_in,
                              void* d_out, int out_size) {
    (void)in_sizes; (void)n_in; (void)out_size;
    const float* x = (const float*)d_in[0];
    float* y = (float*)d_out;
    cudaFuncSetAttribute(gauss_blur_fused,
                         cudaFuncAttributeMaxDynamicSharedMemorySize, SMEM_BYTES);
    dim3 grid(IMG_W / TW, IMG_H / TH, NIMG);  // 8 x 4 x 96
    gauss_blur_fused<<<grid, NTHREADS, SMEM_BYTES>>>(x, y);
}